// round 1
// baseline (speedup 1.0000x reference)
#include <cuda_runtime.h>
#include <math.h>
#include <float.h>

// Problem constants
#define Bc   4
#define Lc   2048
#define Dc   1024
#define Hc   16
#define Fc   4096
#define dHc  64
#define BHc  64      // B*H
#define Uc   2048    // U_part (sampled keys)
#define TOPK 40      // u (selected queries)
#define MR   8192    // B*L rows

// ---------------- scratch (device globals; no allocation allowed) -------------
__device__ float g_Q [MR * Dc];
__device__ float g_K [MR * Dc];
__device__ float g_V [MR * Dc];
__device__ float g_Ks[Bc * Uc * Dc];
__device__ float g_AO[MR * Dc];
__device__ float g_X1[MR * Dc];
__device__ float g_Y1[MR * Fc];
__device__ float g_Y2[MR * Dc];
__device__ float g_M [BHc * Lc];
__device__ int   g_Mtop[BHc * TOPK];
__device__ float g_Or[BHc * TOPK * dHc];

// ---------------- generic fp32 GEMM: C = A(MxK) @ B(KxN) + bias, opt relu -----
__global__ __launch_bounds__(256) void gemm_bias_kernel(
    const float* __restrict__ A, const float* __restrict__ B,
    const float* __restrict__ bias, float* __restrict__ C,
    int M, int N, int K, int relu)
{
    __shared__ float As[8][128];
    __shared__ float Bs[8][128];
    int tid = threadIdx.x;
    int bm = blockIdx.y * 128;
    int bn = blockIdx.x * 128;
    int arow = tid >> 1;
    int acol = (tid & 1) << 2;
    int brow = tid >> 5;
    int bcol = (tid & 31) << 2;
    int tx = tid & 15, ty = tid >> 4;

    float acc[8][8];
#pragma unroll
    for (int i = 0; i < 8; i++)
#pragma unroll
        for (int j = 0; j < 8; j++) acc[i][j] = 0.f;

    const float* Ap = A + (size_t)(bm + arow) * K + acol;
    const float* Bp = B + (size_t)brow * N + bn + bcol;

    for (int k0 = 0; k0 < K; k0 += 8) {
        float4 av = *(const float4*)(Ap + k0);
        float4 bv = *(const float4*)(Bp + (size_t)k0 * N);
        As[acol + 0][arow] = av.x;
        As[acol + 1][arow] = av.y;
        As[acol + 2][arow] = av.z;
        As[acol + 3][arow] = av.w;
        *(float4*)&Bs[brow][bcol] = bv;
        __syncthreads();
#pragma unroll
        for (int kk = 0; kk < 8; kk++) {
            float a[8], b[8];
            *(float4*)(a)     = *(const float4*)&As[kk][ty * 8];
            *(float4*)(a + 4) = *(const float4*)&As[kk][ty * 8 + 4];
            *(float4*)(b)     = *(const float4*)&Bs[kk][tx * 8];
            *(float4*)(b + 4) = *(const float4*)&Bs[kk][tx * 8 + 4];
#pragma unroll
            for (int i = 0; i < 8; i++)
#pragma unroll
                for (int j = 0; j < 8; j++)
                    acc[i][j] = fmaf(a[i], b[j], acc[i][j]);
        }
        __syncthreads();
    }

#pragma unroll
    for (int i = 0; i < 8; i++) {
        int row = bm + ty * 8 + i;
#pragma unroll
        for (int j = 0; j < 8; j++) {
            int col = bn + tx * 8 + j;
            float v = acc[i][j] + bias[col];
            if (relu) v = fmaxf(v, 0.f);
            C[(size_t)row * N + col] = v;
        }
    }
}

// ---------------- gather sampled key rows: Ks[b,j,:] = K[b, idx[j], :] --------
__global__ void gather_kernel(const float* __restrict__ K, const int* __restrict__ idx,
                              float* __restrict__ Ks)
{
    int j = blockIdx.x & (Uc - 1);
    int b = blockIdx.x >> 11;
    int src = idx[j];
    const float4* s = (const float4*)(K + ((size_t)b * Lc + src) * Dc);
    float4* d = (float4*)(Ks + ((size_t)b * Uc + j) * Dc);
    d[threadIdx.x] = s[threadIdx.x];   // 256 threads * float4 = 1024 floats
}

// ---------------- streaming QK stats: M[bh,qi] = max_j QK - mean_j QK --------
__global__ __launch_bounds__(128) void qk_stats_kernel(
    const float* __restrict__ Q, const float* __restrict__ Ks, float* __restrict__ Mout)
{
    int bh = blockIdx.y;
    int b = bh >> 4, h = bh & 15;
    int q0 = blockIdx.x * 32;
    const float* qbase = Q + ((size_t)bh * Lc + q0) * 64;   // contiguous q slice
    const float* kbase = Ks + (size_t)b * Uc * Dc + h * 64;

    __shared__ float qs[64][32];
    __shared__ float ks[64][64];
    int tid = threadIdx.x;

#pragma unroll
    for (int i = 0; i < 4; i++) {
        int f4 = tid + i * 128;        // 0..511
        int qi = f4 >> 4;
        int e  = (f4 & 15) << 2;
        float4 v = *(const float4*)(qbase + (size_t)qi * 64 + e);
        qs[e + 0][qi] = v.x; qs[e + 1][qi] = v.y;
        qs[e + 2][qi] = v.z; qs[e + 3][qi] = v.w;
    }

    int ty = tid >> 4, tx = tid & 15;
    float  runMax[4] = {-FLT_MAX, -FLT_MAX, -FLT_MAX, -FLT_MAX};
    double runSum[4] = {0, 0, 0, 0};

    for (int kt = 0; kt < Uc; kt += 64) {
        __syncthreads();
#pragma unroll
        for (int i = 0; i < 8; i++) {
            int f4 = tid + i * 128;    // 0..1023
            int kj = f4 >> 4;
            int e  = (f4 & 15) << 2;
            float4 v = *(const float4*)(kbase + (size_t)(kt + kj) * Dc + e);
            ks[e + 0][kj] = v.x; ks[e + 1][kj] = v.y;
            ks[e + 2][kj] = v.z; ks[e + 3][kj] = v.w;
        }
        __syncthreads();

        float sc[4][4] = {};
#pragma unroll
        for (int e = 0; e < 64; e++) {
            float a[4], bb[4];
            *(float4*)a  = *(const float4*)&qs[e][ty * 4];
            *(float4*)bb = *(const float4*)&ks[e][tx * 4];
#pragma unroll
            for (int i = 0; i < 4; i++)
#pragma unroll
                for (int j = 0; j < 4; j++)
                    sc[i][j] = fmaf(a[i], bb[j], sc[i][j]);
        }
#pragma unroll
        for (int i = 0; i < 4; i++) {
            float mx = fmaxf(fmaxf(sc[i][0], sc[i][1]), fmaxf(sc[i][2], sc[i][3]));
            runMax[i] = fmaxf(runMax[i], mx);
            runSum[i] += (double)((sc[i][0] + sc[i][1]) + (sc[i][2] + sc[i][3]));
        }
    }

    // reduce across 16-lane half-warps (tx dimension)
#pragma unroll
    for (int off = 8; off > 0; off >>= 1) {
#pragma unroll
        for (int i = 0; i < 4; i++) {
            runMax[i] = fmaxf(runMax[i], __shfl_xor_sync(0xffffffffu, runMax[i], off));
            runSum[i] += __shfl_xor_sync(0xffffffffu, runSum[i], off);
        }
    }
    if (tx == 0) {
#pragma unroll
        for (int i = 0; i < 4; i++)
            Mout[(size_t)bh * Lc + q0 + ty * 4 + i] =
                runMax[i] - (float)(runSum[i] * (1.0 / (double)Lc));
    }
}

// ---------------- top-40 smallest M (ties -> lower index), per bh -------------
__global__ __launch_bounds__(256) void topk_kernel(const float* __restrict__ Mv,
                                                   int* __restrict__ Mtop)
{
    __shared__ float sv[Lc];
    __shared__ float rv[256];
    __shared__ int   ri[256];
    int bh = blockIdx.x, tid = threadIdx.x;
    for (int i = tid; i < Lc; i += 256) sv[i] = Mv[(size_t)bh * Lc + i];
    __syncthreads();

    for (int it = 0; it < TOPK; it++) {
        float bv = FLT_MAX; int bi = 0x7fffffff;
        for (int i = tid; i < Lc; i += 256) {
            float v = sv[i];
            if (v < bv || (v == bv && i < bi)) { bv = v; bi = i; }
        }
        rv[tid] = bv; ri[tid] = bi;
        __syncthreads();
        for (int s = 128; s > 0; s >>= 1) {
            if (tid < s) {
                float v2 = rv[tid + s]; int i2 = ri[tid + s];
                if (v2 < rv[tid] || (v2 == rv[tid] && i2 < ri[tid])) {
                    rv[tid] = v2; ri[tid] = i2;
                }
            }
            __syncthreads();
        }
        if (tid == 0) { Mtop[bh * TOPK + it] = ri[0]; sv[ri[0]] = FLT_MAX; }
        __syncthreads();
    }
}

// ---------------- sparse attention for one selected query -------------------
__global__ __launch_bounds__(128) void sparse_attn_kernel(
    const float* __restrict__ Q, const float* __restrict__ K, const float* __restrict__ V,
    const int* __restrict__ Mtop, float* __restrict__ outred)
{
    int ui = blockIdx.x, bh = blockIdx.y;
    int b = bh >> 4, h = bh & 15;
    int qi = Mtop[bh * TOPK + ui];

    __shared__ float qsh[64];
    __shared__ float wm[4], ws[4], wa[4][64];
    int tid = threadIdx.x, warp = tid >> 5, lane = tid & 31;
    if (tid < 64) qsh[tid] = Q[((size_t)bh * Lc + qi) * 64 + tid];
    __syncthreads();

    float q0v = qsh[lane], q1v = qsh[lane + 32];
    float m = -FLT_MAX, s = 0.f, a0 = 0.f, a1 = 0.f;
    const float* kb = K + (size_t)b * Lc * Dc + h * 64;
    const float* vb = V + (size_t)b * Lc * Dc + h * 64;

    for (int l = warp * 512; l < warp * 512 + 512; l++) {
        const float* kr = kb + (size_t)l * Dc;
        float p = q0v * kr[lane] + q1v * kr[lane + 32];
#pragma unroll
        for (int off = 16; off > 0; off >>= 1)
            p += __shfl_xor_sync(0xffffffffu, p, off);
        p *= 0.125f;                            // 1/sqrt(64)
        float mn = fmaxf(m, p);
        float c = expf(m - mn);
        float w = expf(p - mn);
        const float* vr = vb + (size_t)l * Dc;
        s  = s * c + w;
        a0 = a0 * c + w * vr[lane];
        a1 = a1 * c + w * vr[lane + 32];
        m = mn;
    }
    if (lane == 0) { wm[warp] = m; ws[warp] = s; }
    wa[warp][lane] = a0; wa[warp][lane + 32] = a1;
    __syncthreads();

    if (tid < 64) {
        float gm = fmaxf(fmaxf(wm[0], wm[1]), fmaxf(wm[2], wm[3]));
        float gs = 0.f, ga = 0.f;
#pragma unroll
        for (int w2 = 0; w2 < 4; w2++) {
            float f = expf(wm[w2] - gm);
            gs += ws[w2] * f;
            ga += wa[w2][tid] * f;
        }
        outred[((size_t)bh * TOPK + ui) * 64 + tid] = ga / gs;
    }
}

// ---------------- AO init with bo (the all-zero rows of full@wo) -------------
__global__ void init_bias_kernel(const float* __restrict__ bo, float* __restrict__ AO)
{
    float4 v = *(const float4*)(bo + threadIdx.x * 4);
    *(float4*)(AO + (size_t)blockIdx.x * Dc + threadIdx.x * 4) = v;
}

// ---------------- sparse output projection: AO[b,l,:] += out_red @ wo_headblk --
__global__ __launch_bounds__(256) void sparse_proj_kernel(
    const float* __restrict__ outred, const int* __restrict__ Mtop,
    const float* __restrict__ wo, float* __restrict__ AO)
{
    int ui = blockIdx.x, bh = blockIdx.y;
    int b = bh >> 4, h = bh & 15;
    int l = Mtop[bh * TOPK + ui];
    __shared__ float r[64];
    int tid = threadIdx.x;
    if (tid < 64) r[tid] = outred[((size_t)bh * TOPK + ui) * 64 + tid];
    __syncthreads();

    float acc0 = 0.f, acc1 = 0.f, acc2 = 0.f, acc3 = 0.f;
    const float* w = wo + (size_t)h * 64 * Dc + tid;
#pragma unroll 8
    for (int e = 0; e < 64; e++) {
        float re = r[e];
        const float* wr = w + (size_t)e * Dc;
        acc0 = fmaf(re, wr[0],   acc0);
        acc1 = fmaf(re, wr[256], acc1);
        acc2 = fmaf(re, wr[512], acc2);
        acc3 = fmaf(re, wr[768], acc3);
    }
    float* dst = AO + ((size_t)b * Lc + l) * Dc + tid;
    atomicAdd(dst,       acc0);
    atomicAdd(dst + 256, acc1);
    atomicAdd(dst + 512, acc2);
    atomicAdd(dst + 768, acc3);
}

// ---------------- residual add + LayerNorm ------------------------------------
__global__ __launch_bounds__(256) void add_ln_kernel(
    const float* __restrict__ X, const float* __restrict__ Y,
    const float* __restrict__ g, const float* __restrict__ be, float* __restrict__ out)
{
    int row = blockIdx.x, tid = threadIdx.x;
    __shared__ float red[256];
    float v[4];
    float s = 0.f;
#pragma unroll
    for (int c = 0; c < 4; c++) {
        size_t i = (size_t)row * Dc + tid + c * 256;
        v[c] = X[i] + Y[i];
        s += v[c];
    }
    red[tid] = s; __syncthreads();
    for (int st = 128; st > 0; st >>= 1) {
        if (tid < st) red[tid] += red[tid + st];
        __syncthreads();
    }
    float mean = red[0] * (1.f / 1024.f);
    __syncthreads();

    float s2 = 0.f;
#pragma unroll
    for (int c = 0; c < 4; c++) { float t = v[c] - mean; s2 = fmaf(t, t, s2); }
    red[tid] = s2; __syncthreads();
    for (int st = 128; st > 0; st >>= 1) {
        if (tid < st) red[tid] += red[tid + st];
        __syncthreads();
    }
    float var = red[0] * (1.f / 1024.f);
    float rstd = 1.0f / sqrtf(var + 1e-12f);

#pragma unroll
    for (int c = 0; c < 4; c++) {
        int col = tid + c * 256;
        out[(size_t)row * Dc + col] = g[col] * ((v[c] - mean) * rstd) + be[col];
    }
}

// ---------------- launch --------------------------------------------------------
extern "C" void kernel_launch(void* const* d_in, const int* in_sizes, int n_in,
                              void* d_out, int out_size)
{
    const float* x   = (const float*)d_in[0];
    const float* wq  = (const float*)d_in[1];
    const float* bq  = (const float*)d_in[2];
    const float* wk  = (const float*)d_in[3];
    const float* bk  = (const float*)d_in[4];
    const float* wv  = (const float*)d_in[5];
    const float* bv  = (const float*)d_in[6];
    const float* wo  = (const float*)d_in[7];
    const float* bo  = (const float*)d_in[8];
    const float* w1  = (const float*)d_in[9];
    const float* b1  = (const float*)d_in[10];
    const float* w2  = (const float*)d_in[11];
    const float* b2  = (const float*)d_in[12];
    const float* ga1 = (const float*)d_in[13];
    const float* be1 = (const float*)d_in[14];
    const float* ga2 = (const float*)d_in[15];
    const float* be2 = (const float*)d_in[16];
    const int*   idx = (const int*)d_in[17];
    float* out = (float*)d_out;

    float *Q, *K, *V, *Ks, *AO, *X1, *Y1, *Y2, *Mv, *Or;
    int* Mt;
    cudaGetSymbolAddress((void**)&Q,  g_Q);
    cudaGetSymbolAddress((void**)&K,  g_K);
    cudaGetSymbolAddress((void**)&V,  g_V);
    cudaGetSymbolAddress((void**)&Ks, g_Ks);
    cudaGetSymbolAddress((void**)&AO, g_AO);
    cudaGetSymbolAddress((void**)&X1, g_X1);
    cudaGetSymbolAddress((void**)&Y1, g_Y1);
    cudaGetSymbolAddress((void**)&Y2, g_Y2);
    cudaGetSymbolAddress((void**)&Mv, g_M);
    cudaGetSymbolAddress((void**)&Mt, g_Mtop);
    cudaGetSymbolAddress((void**)&Or, g_Or);

    dim3 gD(Dc / 128, MR / 128);   // (8, 64)
    dim3 gF(Fc / 128, MR / 128);   // (32, 64)

    // QKV projections
    gemm_bias_kernel<<<gD, 256>>>(x, wq, bq, Q, MR, Dc, Dc, 0);
    gemm_bias_kernel<<<gD, 256>>>(x, wk, bk, K, MR, Dc, Dc, 0);
    gemm_bias_kernel<<<gD, 256>>>(x, wv, bv, V, MR, Dc, Dc, 0);

    // ProbSparse selection
    gather_kernel<<<Bc * Uc, 256>>>(K, idx, Ks);
    qk_stats_kernel<<<dim3(Lc / 32, BHc), 128>>>(Q, Ks, Mv);
    topk_kernel<<<BHc, 256>>>(Mv, Mt);

    // Sparse attention over selected queries
    sparse_attn_kernel<<<dim3(TOPK, BHc), 128>>>(Q, K, V, Mt, Or);

    // Sparse output projection (full @ wo + bo, exploiting zero rows)
    init_bias_kernel<<<MR, 256>>>(bo, AO);
    sparse_proj_kernel<<<dim3(TOPK, BHc), 256>>>(Or, Mt, wo, AO);

    // Residual + LN1
    add_ln_kernel<<<MR, 256>>>(x, AO, ga1, be1, X1);

    // FFN
    gemm_bias_kernel<<<gF, 256>>>(X1, w1, b1, Y1, MR, Fc, Dc, 1);
    gemm_bias_kernel<<<gD, 256>>>(Y1, w2, b2, Y2, MR, Dc, Fc, 0);

    // Residual + LN2 -> output
    add_ln_kernel<<<MR, 256>>>(X1, Y2, ga2, be2, out);
}